// round 1
// baseline (speedup 1.0000x reference)
#include <cuda_runtime.h>
#include <cstdint>
#include <cstddef>

// Problem constants
#define BATCH   2048
#define HIDDEN  1024
#define FFN     4096
#define NEXP    8
#define TOPK    2
#define NPAIR   (BATCH * TOPK)      // 4096
#define MAXMB   64                  // upper bound on M-blocks (<= 8 + 4096/128 = 40)

// ---------------- device scratch (static globals; no allocation) ----------------
__device__ int   g_off[NEXP + 1];
__device__ int   g_num_mb;
__device__ int   g_blk_e[MAXMB];
__device__ int   g_blk_r0[MAXMB];
__device__ int   g_tok[NPAIR];
__device__ float g_w[NPAIR];
__device__ float g_hbuf[(size_t)NPAIR * FFN];   // 64 MiB intermediate (post-SiLU)

// ---------------- helpers ----------------
__device__ __forceinline__ uint32_t f2tf(float f) {
    uint32_t r;
    asm("cvt.rna.tf32.f32 %0, %1;" : "=r"(r) : "f"(f));
    return r;
}

__device__ __forceinline__ void mma_tf32(float c[4], const uint32_t a[4], const uint32_t b[2]) {
    asm volatile(
        "mma.sync.aligned.m16n8k8.row.col.f32.tf32.tf32.f32 "
        "{%0,%1,%2,%3}, {%4,%5,%6,%7}, {%8,%9}, {%0,%1,%2,%3};\n"
        : "+f"(c[0]), "+f"(c[1]), "+f"(c[2]), "+f"(c[3])
        : "r"(a[0]), "r"(a[1]), "r"(a[2]), "r"(a[3]), "r"(b[0]), "r"(b[1]));
}

// ---------------- kernel: zero output ----------------
__global__ void zero_out_kernel(float* __restrict__ out) {
    size_t i = (size_t)blockIdx.x * blockDim.x + threadIdx.x;   // 524288 threads
    reinterpret_cast<float4*>(out)[i] = make_float4(0.f, 0.f, 0.f, 0.f);
}

// ---------------- kernel: routing (single block) ----------------
__global__ void route_kernel(const int* __restrict__ idx32, const float* __restrict__ rw) {
    __shared__ int s_cnt[NEXP];
    __shared__ int s_fill[NEXP];
    __shared__ int s_off[NEXP + 1];
    __shared__ int s_is64;
    const int tid = threadIdx.x;

    if (tid < NEXP) { s_cnt[tid] = 0; s_fill[tid] = 0; }
    if (tid == 0) {
        // Detect int64 vs int32 storage: int64 values 0..7 have zero upper words.
        int any = 0;
        for (int i = 0; i < 64; i++) any |= idx32[2 * i + 1];
        s_is64 = (any == 0) ? 1 : 0;
    }
    __syncthreads();
    const int is64 = s_is64;

    for (int i = tid; i < NPAIR; i += blockDim.x) {
        int e = is64 ? idx32[2 * i] : idx32[i];
        atomicAdd(&s_cnt[e], 1);
    }
    __syncthreads();

    if (tid == 0) {
        int acc = 0, nb = 0;
        s_off[0] = 0;
        for (int e = 0; e < NEXP; e++) {
            for (int r = 0; r < s_cnt[e]; r += 128) {
                g_blk_e[nb] = e;
                g_blk_r0[nb] = acc + r;
                nb++;
            }
            acc += s_cnt[e];
            s_off[e + 1] = acc;
        }
        g_num_mb = nb;
        for (int e = 0; e <= NEXP; e++) g_off[e] = s_off[e];
    }
    __syncthreads();

    for (int i = tid; i < NPAIR; i += blockDim.x) {
        int e = is64 ? idx32[2 * i] : idx32[i];
        int pos = s_off[e] + atomicAdd(&s_fill[e], 1);
        g_tok[pos] = i >> 1;   // token index (i = token*TOPK + slot)
        g_w[pos]   = rw[i];
    }
}

// ---------------- grouped GEMM ----------------
// MODE 1:  h[p, 0:FFN]  = silu( x[tok(p), :] @ w1[e] ),   K=1024, N=4096
// MODE 2:  out[tok(p)] += w(p) * ( h[p, :] @ w2[e] ),     K=4096, N=1024
// Block tile 128x128, K-tile 32. 256 threads = 8 warps in 2(M) x 4(N),
// each warp 64x32 = 4x4 tiles of m16n8k8 tf32 mma.
template <int MODE>
__global__ __launch_bounds__(256, 2)
void moe_gemm(const float* __restrict__ X, const float* __restrict__ W,
              float* __restrict__ OUT) {
    constexpr int KDIM = (MODE == 1) ? HIDDEN : FFN;
    constexpr int NDIM = (MODE == 1) ? FFN : HIDDEN;
    constexpr int AS_STRIDE = 36;    // 128 rows x (32 + pad) -> conflict-free frag loads
    constexpr int BS_STRIDE = 136;   // 32 rows x (128 + pad) -> conflict-free frag loads

    const int mb = blockIdx.y;
    if (mb >= g_num_mb) return;
    const int e      = g_blk_e[mb];
    const int row0   = g_blk_r0[mb];
    const int rowEnd = g_off[e + 1];
    const int n0     = blockIdx.x * 128;

    const float* __restrict__ B = W + (size_t)e * (size_t)KDIM * (size_t)NDIM;

    __shared__ uint32_t As[128 * AS_STRIDE];
    __shared__ uint32_t Bs[32 * BS_STRIDE];

    const int tid = threadIdx.x;

    // A-row base pointers (gathered for MODE 1; contiguous scratch rows for MODE 2)
    const float* arow[4];
#pragma unroll
    for (int i = 0; i < 4; i++) {
        int r = (tid >> 3) + i * 32;
        int p = row0 + r;
        if (p >= rowEnd) p = rowEnd - 1;   // clamp; results discarded in epilogue
        if (MODE == 1) arow[i] = X + (size_t)g_tok[p] * HIDDEN;
        else           arow[i] = g_hbuf + (size_t)p * FFN;
    }
    const int acol = (tid & 7) * 4;      // float col of A float4 load
    const int brow = tid >> 3;           // 0..31
    const int bcol = (tid & 7) * 4;      // + i*32

    float c[4][4][4];
#pragma unroll
    for (int a = 0; a < 4; a++)
#pragma unroll
        for (int b = 0; b < 4; b++)
#pragma unroll
            for (int d = 0; d < 4; d++) c[a][b][d] = 0.f;

    const int warp = tid >> 5, lane = tid & 31;
    const int wm = (warp & 1) * 64, wn = (warp >> 1) * 32;
    const int grp = lane >> 2, tg = lane & 3;

    for (int k0 = 0; k0 < KDIM; k0 += 32) {
        // ---- stage A tile (128 x 32) ----
#pragma unroll
        for (int i = 0; i < 4; i++) {
            float4 v = *reinterpret_cast<const float4*>(arow[i] + k0 + acol);
            int r = (tid >> 3) + i * 32;
            uint32_t* dst = &As[r * AS_STRIDE + acol];
            dst[0] = f2tf(v.x); dst[1] = f2tf(v.y); dst[2] = f2tf(v.z); dst[3] = f2tf(v.w);
        }
        // ---- stage B tile (32 x 128) ----
        const float* bsrc = B + (size_t)(k0 + brow) * NDIM + n0;
#pragma unroll
        for (int i = 0; i < 4; i++) {
            int cf = bcol + i * 32;
            float4 v = *reinterpret_cast<const float4*>(bsrc + cf);
            uint32_t* dst = &Bs[brow * BS_STRIDE + cf];
            dst[0] = f2tf(v.x); dst[1] = f2tf(v.y); dst[2] = f2tf(v.z); dst[3] = f2tf(v.w);
        }
        __syncthreads();

        // ---- compute: 4 k-steps of 8 ----
#pragma unroll
        for (int ks = 0; ks < 4; ks++) {
            uint32_t a[4][4];
#pragma unroll
            for (int mt = 0; mt < 4; mt++) {
                const uint32_t* ap = &As[(wm + mt * 16 + grp) * AS_STRIDE + ks * 8 + tg];
                a[mt][0] = ap[0];
                a[mt][1] = ap[8 * AS_STRIDE];
                a[mt][2] = ap[4];
                a[mt][3] = ap[8 * AS_STRIDE + 4];
            }
            uint32_t b[4][2];
#pragma unroll
            for (int nt = 0; nt < 4; nt++) {
                const uint32_t* bp = &Bs[(ks * 8 + tg) * BS_STRIDE + wn + nt * 8 + grp];
                b[nt][0] = bp[0];
                b[nt][1] = bp[4 * BS_STRIDE];
            }
#pragma unroll
            for (int mt = 0; mt < 4; mt++)
#pragma unroll
                for (int nt = 0; nt < 4; nt++)
                    mma_tf32(c[mt][nt], a[mt], b[nt]);
        }
        __syncthreads();
    }

    // ---- epilogue ----
#pragma unroll
    for (int mt = 0; mt < 4; mt++) {
        const int rbase = wm + mt * 16 + grp;
#pragma unroll
        for (int nt = 0; nt < 4; nt++) {
            const int col = n0 + wn + nt * 8 + tg * 2;
#pragma unroll
            for (int half = 0; half < 2; half++) {
                const int r = rbase + half * 8;
                const int p = row0 + r;
                if (p < rowEnd) {
                    float v0 = c[mt][nt][half * 2 + 0];
                    float v1 = c[mt][nt][half * 2 + 1];
                    if (MODE == 1) {
                        float s0 = v0 / (1.f + expf(-v0));
                        float s1 = v1 / (1.f + expf(-v1));
                        *reinterpret_cast<float2*>(&g_hbuf[(size_t)p * FFN + col]) =
                            make_float2(s0, s1);
                    } else {
                        const float w = g_w[p];
                        const int   t = g_tok[p];
                        atomicAdd(&OUT[(size_t)t * HIDDEN + col],     v0 * w);
                        atomicAdd(&OUT[(size_t)t * HIDDEN + col + 1], v1 * w);
                    }
                }
            }
        }
    }
}

// ---------------- launch ----------------
extern "C" void kernel_launch(void* const* d_in, const int* in_sizes, int n_in,
                              void* d_out, int out_size) {
    const float* x   = (const float*)d_in[0];   // [2048,1024]
    const float* rw  = (const float*)d_in[1];   // [2048,2]
    const float* w1  = (const float*)d_in[2];   // [8,1024,4096]
    const float* w2  = (const float*)d_in[3];   // [8,4096,1024]
    const int*   idx = (const int*)d_in[4];     // [2048,2] (int32 or int64, auto-detected)
    float* out = (float*)d_out;                 // [2048,1024]

    zero_out_kernel<<<2048, 256>>>(out);        // 2048*256 = 524288 float4 = full output
    route_kernel<<<1, 256>>>(idx, rw);
    moe_gemm<1><<<dim3(FFN / 128, 40), 256>>>(x, w1, nullptr);
    moe_gemm<2><<<dim3(HIDDEN / 128, 40), 256>>>(nullptr, w2, out);
}

// round 3
// speedup vs baseline: 1.6583x; 1.6583x over previous
#include <cuda_runtime.h>
#include <cuda_fp16.h>
#include <cstdint>
#include <cstddef>

#define BATCH   2048
#define HIDDEN  1024
#define FFN     4096
#define NEXP    8
#define TOPK    2
#define NPAIR   (BATCH * TOPK)
#define MAXMB   64
#define KSPLIT  4

// ---------------- device scratch ----------------
__device__ int    g_off[NEXP + 1];
__device__ int    g_num_mb;
__device__ int    g_blk_e[MAXMB];
__device__ int    g_blk_r0[MAXMB];
__device__ int    g_tok[NPAIR];
__device__ int    g_ppos[NPAIR];
__device__ float  g_w[NPAIR];
__device__ __half g_hbuf[(size_t)NPAIR * FFN];                    // 32 MiB fp16
__device__ float  g_ybuf[(size_t)KSPLIT * NPAIR * HIDDEN];        // 64 MiB fp32

// ---------------- helpers ----------------
__device__ __forceinline__ uint32_t smem_u32(const void* p) {
    uint32_t a;
    asm("{ .reg .u64 t; cvta.to.shared.u64 t, %1; cvt.u32.u64 %0, t; }" : "=r"(a) : "l"(p));
    return a;
}
__device__ __forceinline__ uint32_t pk_f16x2(float lo, float hi) {
    uint32_t r;
    asm("cvt.rn.f16x2.f32 %0, %1, %2;" : "=r"(r) : "f"(hi), "f"(lo));
    return r;
}
__device__ __forceinline__ void ldmx4(uint32_t* d, uint32_t addr) {
    asm volatile("ldmatrix.sync.aligned.m8n8.x4.shared.b16 {%0,%1,%2,%3}, [%4];"
                 : "=r"(d[0]), "=r"(d[1]), "=r"(d[2]), "=r"(d[3]) : "r"(addr));
}
__device__ __forceinline__ void ldmx4t(uint32_t* d, uint32_t addr) {
    asm volatile("ldmatrix.sync.aligned.m8n8.x4.trans.shared.b16 {%0,%1,%2,%3}, [%4];"
                 : "=r"(d[0]), "=r"(d[1]), "=r"(d[2]), "=r"(d[3]) : "r"(addr));
}
__device__ __forceinline__ void mma_f16(float* c, const uint32_t* a, uint32_t b0, uint32_t b1) {
    asm volatile(
        "mma.sync.aligned.m16n8k16.row.col.f32.f16.f16.f32 "
        "{%0,%1,%2,%3}, {%4,%5,%6,%7}, {%8,%9}, {%0,%1,%2,%3};"
        : "+f"(c[0]), "+f"(c[1]), "+f"(c[2]), "+f"(c[3])
        : "r"(a[0]), "r"(a[1]), "r"(a[2]), "r"(a[3]), "r"(b0), "r"(b1));
}

// smem layouts (per stage, 24 KiB):
//   As: 8 KiB, fp16 [128 m][32 k]; addr(m,kc8) = (m>>1)*128 + (((m&1)*4+kc) ^ ((m>>1)&7))*16
//   Bs: 16 KiB at +8192, fp16 [32 k][256 n]; addr(k,nc8) = k*512 + ((nc ^ (k&7)))*16
__device__ __forceinline__ uint32_t a_addr(int m, int kc) {
    return (uint32_t)((m >> 1) * 128 + (((((m & 1) << 2) | kc) ^ ((m >> 1) & 7)) << 4));
}
__device__ __forceinline__ uint32_t b_addr(int k, int nc) {
    return (uint32_t)(8192 + k * 512 + (((nc ^ (k & 7))) << 4));
}

// ---------------- routing ----------------
__global__ void route_kernel(const int* __restrict__ idx32, const float* __restrict__ rw) {
    __shared__ int s_cnt[NEXP];
    __shared__ int s_fill[NEXP];
    __shared__ int s_off[NEXP + 1];
    __shared__ int s_is64;
    const int tid = threadIdx.x;

    if (tid < NEXP) { s_cnt[tid] = 0; s_fill[tid] = 0; }
    if (tid == 0) {
        int any = 0;
        for (int i = 0; i < 64; i++) any |= idx32[2 * i + 1];
        s_is64 = (any == 0) ? 1 : 0;
    }
    __syncthreads();
    const int is64 = s_is64;

    for (int i = tid; i < NPAIR; i += blockDim.x) {
        int e = is64 ? idx32[2 * i] : idx32[i];
        atomicAdd(&s_cnt[e], 1);
    }
    __syncthreads();

    if (tid == 0) {
        int acc = 0, nb = 0;
        s_off[0] = 0;
        for (int e = 0; e < NEXP; e++) {
            for (int r = 0; r < s_cnt[e]; r += 128) {
                g_blk_e[nb] = e; g_blk_r0[nb] = acc + r; nb++;
            }
            acc += s_cnt[e];
            s_off[e + 1] = acc;
        }
        g_num_mb = nb;
        for (int e = 0; e <= NEXP; e++) g_off[e] = s_off[e];
    }
    __syncthreads();

    for (int i = tid; i < NPAIR; i += blockDim.x) {
        int e = is64 ? idx32[2 * i] : idx32[i];
        int pos = s_off[e] + atomicAdd(&s_fill[e], 1);
        g_tok[pos] = i >> 1;
        g_w[pos]   = rw[i];
        g_ppos[i]  = pos;
    }
}

// ---------------- grouped GEMM (fp16 mma, fp32 accum) ----------------
// MODE 1: h[p] = silu(x[tok(p)] @ w1[e])          K=1024          -> g_hbuf (fp16)
// MODE 2: yb[z][p] = w(p)*(h[p, z*1024:+1024] @ w2[e][z*1024:+1024, :]) -> g_ybuf
// CTA tile 128(M) x 256(N), k-tile 32, K per CTA = 1024 (32 k-tiles).
// 256 threads = 8 warps (2M x 4N), warp tile 64x64.
template <int MODE>
__global__ __launch_bounds__(256, 1)
void moe_mma(const float* __restrict__ X, const float* __restrict__ W) {
    constexpr int NDIM = (MODE == 1) ? FFN : HIDDEN;
    constexpr int KFULL = (MODE == 1) ? HIDDEN : FFN;

    __shared__ __align__(128) uint8_t smbuf[2][24576];

    const int mb = blockIdx.x;
    if (mb >= g_num_mb) return;
    const int e      = g_blk_e[mb];
    const int row0   = g_blk_r0[mb];
    const int rowEnd = g_off[e + 1];
    const int n0     = blockIdx.y * 256;
    const int kbase  = (MODE == 2) ? blockIdx.z * 1024 : 0;
    const float* __restrict__ We =
        W + (size_t)e * KFULL * NDIM + (size_t)kbase * NDIM;

    const int tid = threadIdx.x, lane = tid & 31, warp = tid >> 5;
    const int wm = (warp & 1) * 64, wn = (warp >> 1) * 64;
    const uint32_t smb = smem_u32(&smbuf[0][0]);

    // ---- staging assignments ----
    // A: 2 units/thread, unit = 1 row x 8 k
    const float*  aPf[2];
    const __half* aPh[2];
    uint32_t aoff[2];
#pragma unroll
    for (int i = 0; i < 2; i++) {
        int u = tid + i * 256;
        int m = u >> 2, kc = u & 3;
        int p = row0 + m; if (p >= rowEnd) p = rowEnd - 1;
        if (MODE == 1) aPf[i] = X + (size_t)g_tok[p] * HIDDEN + kc * 8;
        else           aPh[i] = g_hbuf + (size_t)p * FFN + kbase + kc * 8;
        aoff[i] = a_addr(m, kc);
    }
    // B: 4 units/thread, unit = 1 k x 8 n
    const float* bPf[4];
    uint32_t boff[4];
#pragma unroll
    for (int i = 0; i < 4; i++) {
        int u = tid + i * 256;
        int k = u >> 5, nc = u & 31;
        bPf[i] = We + (size_t)k * NDIM + n0 + nc * 8;
        boff[i] = b_addr(k, nc);
    }

    // ---- fragment addresses (per-lane, per mt/ntp per kstep) ----
    const int g = lane >> 3, r = lane & 7;
    uint32_t aFrag[4][2], bFrag[4][2];
#pragma unroll
    for (int mt = 0; mt < 4; mt++) {
        int m = wm + mt * 16 + (g & 1) * 8 + r;
#pragma unroll
        for (int ks = 0; ks < 2; ks++)
            aFrag[mt][ks] = a_addr(m, ks * 2 + (g >> 1));
    }
#pragma unroll
    for (int ntp = 0; ntp < 4; ntp++) {
#pragma unroll
        for (int ks = 0; ks < 2; ks++) {
            int k = ks * 16 + (g & 1) * 8 + r;
            int nc = (wn >> 3) + ntp * 2 + (g >> 1);
            bFrag[ntp][ks] = b_addr(k, nc);
        }
    }

    float C[4][8][4];
#pragma unroll
    for (int a = 0; a < 4; a++)
#pragma unroll
        for (int b = 0; b < 8; b++)
#pragma unroll
            for (int d = 0; d < 4; d++) C[a][b][d] = 0.f;

    // staged registers
    float a_st[2][8];
    uint4 a_sth[2];
    float b_st[4][8];

    auto ldg_tile = [&](int kt) {
        const int k0 = kt * 32;
        if (MODE == 1) {
#pragma unroll
            for (int i = 0; i < 2; i++) {
                float4 v0 = *reinterpret_cast<const float4*>(aPf[i] + k0);
                float4 v1 = *reinterpret_cast<const float4*>(aPf[i] + k0 + 4);
                a_st[i][0] = v0.x; a_st[i][1] = v0.y; a_st[i][2] = v0.z; a_st[i][3] = v0.w;
                a_st[i][4] = v1.x; a_st[i][5] = v1.y; a_st[i][6] = v1.z; a_st[i][7] = v1.w;
            }
        } else {
#pragma unroll
            for (int i = 0; i < 2; i++)
                a_sth[i] = *reinterpret_cast<const uint4*>(aPh[i] + k0);
        }
        const size_t bk = (size_t)k0 * NDIM;
#pragma unroll
        for (int i = 0; i < 4; i++) {
            float4 v0 = *reinterpret_cast<const float4*>(bPf[i] + bk);
            float4 v1 = *reinterpret_cast<const float4*>(bPf[i] + bk + 4);
            b_st[i][0] = v0.x; b_st[i][1] = v0.y; b_st[i][2] = v0.z; b_st[i][3] = v0.w;
            b_st[i][4] = v1.x; b_st[i][5] = v1.y; b_st[i][6] = v1.z; b_st[i][7] = v1.w;
        }
    };

    auto sts_tile = [&](int buf) {
        const uint32_t sb = smb + buf * 24576;
#pragma unroll
        for (int i = 0; i < 2; i++) {
            uint4 u;
            if (MODE == 1) {
                u.x = pk_f16x2(a_st[i][0], a_st[i][1]);
                u.y = pk_f16x2(a_st[i][2], a_st[i][3]);
                u.z = pk_f16x2(a_st[i][4], a_st[i][5]);
                u.w = pk_f16x2(a_st[i][6], a_st[i][7]);
            } else u = a_sth[i];
            asm volatile("st.shared.v4.b32 [%0], {%1,%2,%3,%4};"
                         :: "r"(sb + aoff[i]), "r"(u.x), "r"(u.y), "r"(u.z), "r"(u.w));
        }
#pragma unroll
        for (int i = 0; i < 4; i++) {
            uint32_t x0 = pk_f16x2(b_st[i][0], b_st[i][1]);
            uint32_t x1 = pk_f16x2(b_st[i][2], b_st[i][3]);
            uint32_t x2 = pk_f16x2(b_st[i][4], b_st[i][5]);
            uint32_t x3 = pk_f16x2(b_st[i][6], b_st[i][7]);
            asm volatile("st.shared.v4.b32 [%0], {%1,%2,%3,%4};"
                         :: "r"(sb + boff[i]), "r"(x0), "r"(x1), "r"(x2), "r"(x3));
        }
    };

    auto compute = [&](int buf) {
        const uint32_t sb = smb + buf * 24576;
#pragma unroll
        for (int ks = 0; ks < 2; ks++) {
            uint32_t af[4][4];
#pragma unroll
            for (int mt = 0; mt < 4; mt++) ldmx4(af[mt], sb + aFrag[mt][ks]);
            uint32_t bf[4][4];
#pragma unroll
            for (int ntp = 0; ntp < 4; ntp++) ldmx4t(bf[ntp], sb + bFrag[ntp][ks]);
#pragma unroll
            for (int mt = 0; mt < 4; mt++)
#pragma unroll
                for (int nt = 0; nt < 8; nt++)
                    mma_f16(C[mt][nt], af[mt], bf[nt >> 1][(nt & 1) * 2],
                            bf[nt >> 1][(nt & 1) * 2 + 1]);
        }
    };

    // ---- pipelined main loop (32 k-tiles) ----
    ldg_tile(0);
    sts_tile(0);
    __syncthreads();
#pragma unroll 1
    for (int kt = 0; kt < 32; kt++) {
        const int buf = kt & 1;
        if (kt + 1 < 32) ldg_tile(kt + 1);
        compute(buf);
        if (kt + 1 < 32) sts_tile(buf ^ 1);
        __syncthreads();
    }

    // ---- epilogue ----
    const int grp = lane >> 2, tg = lane & 3;
#pragma unroll
    for (int mt = 0; mt < 4; mt++) {
#pragma unroll
        for (int half = 0; half < 2; half++) {
            const int rowm = wm + mt * 16 + grp + half * 8;
            const int p = row0 + rowm;
            if (p < rowEnd) {
                float wgt = 0.f;
                if (MODE == 2) wgt = g_w[p];
#pragma unroll
                for (int nt = 0; nt < 8; nt++) {
                    float v0 = C[mt][nt][half * 2 + 0];
                    float v1 = C[mt][nt][half * 2 + 1];
                    const int col = n0 + wn + nt * 8 + 2 * tg;
                    if (MODE == 1) {
                        float s0 = v0 / (1.f + __expf(-v0));
                        float s1 = v1 / (1.f + __expf(-v1));
                        *reinterpret_cast<uint32_t*>(&g_hbuf[(size_t)p * FFN + col]) =
                            pk_f16x2(s0, s1);
                    } else {
                        float* dst = g_ybuf +
                            ((size_t)blockIdx.z * NPAIR + p) * HIDDEN + col;
                        *reinterpret_cast<float2*>(dst) = make_float2(v0 * wgt, v1 * wgt);
                    }
                }
            }
        }
    }
}

// ---------------- combine ----------------
__global__ void combine_kernel(float* __restrict__ out) {
    const int t = blockIdx.x;
    const int c = threadIdx.x * 4;
    const int p0 = g_ppos[2 * t], p1 = g_ppos[2 * t + 1];
    float4 acc = make_float4(0.f, 0.f, 0.f, 0.f);
#pragma unroll
    for (int s = 0; s < KSPLIT; s++) {
        const float4 a = *reinterpret_cast<const float4*>(
            g_ybuf + ((size_t)s * NPAIR + p0) * HIDDEN + c);
        const float4 b = *reinterpret_cast<const float4*>(
            g_ybuf + ((size_t)s * NPAIR + p1) * HIDDEN + c);
        acc.x += a.x + b.x; acc.y += a.y + b.y;
        acc.z += a.z + b.z; acc.w += a.w + b.w;
    }
    *reinterpret_cast<float4*>(out + (size_t)t * HIDDEN + c) = acc;
}

// ---------------- launch ----------------
extern "C" void kernel_launch(void* const* d_in, const int* in_sizes, int n_in,
                              void* d_out, int out_size) {
    const float* x   = (const float*)d_in[0];
    const float* rw  = (const float*)d_in[1];
    const float* w1  = (const float*)d_in[2];
    const float* w2  = (const float*)d_in[3];
    const int*   idx = (const int*)d_in[4];
    float* out = (float*)d_out;

    route_kernel<<<1, 256>>>(idx, rw);
    moe_mma<1><<<dim3(40, FFN / 256, 1), 256>>>(x, w1);
    moe_mma<2><<<dim3(40, HIDDEN / 256, KSPLIT), 256>>>(nullptr, w2);
    combine_kernel<<<BATCH, 256>>>(out);
}